// round 13
// baseline (speedup 1.0000x reference)
#include <cuda_runtime.h>
#include <cuda_bf16.h>
#include <math.h>
#include <stdint.h>

// Problem constants (QwenGroupedQueryAttention_44100724195922)
#define BB   2
#define TT   2048
#define EE   2048
#define HH   16
#define DD   128
#define GG   4
#define NKVH 4
#define KVD  512
#define N1   3072
#define MM   4096

__device__ float g_qkv[(size_t)MM * N1];             // fp32 (Q region used)
__device__ float g_k[(size_t)BB * NKVH * TT * DD];   // tf32 bits
__device__ float g_v[(size_t)BB * NKVH * TT * DD];   // tf32 bits
__device__ float g_y[(size_t)MM * EE];               // tf32 bits (attn out)
__device__ float g_wat[(size_t)N1 * EE];             // Wa^T [N1][E] tf32 bits
__device__ float g_wpt[(size_t)EE * EE];             // Wp^T [E][E] tf32 bits

__device__ __forceinline__ uint32_t f2tf32(float x) {
    uint32_t r;
    asm("cvt.rna.tf32.f32 %0, %1;" : "=r"(r) : "f"(x));
    return r;
}

__device__ __forceinline__ void mma_tf32(float c[4], const uint32_t a[4],
                                         uint32_t b0, uint32_t b1) {
    asm volatile(
        "mma.sync.aligned.m16n8k8.row.col.f32.tf32.tf32.f32 "
        "{%0,%1,%2,%3}, {%4,%5,%6,%7}, {%8,%9}, {%0,%1,%2,%3};"
        : "+f"(c[0]), "+f"(c[1]), "+f"(c[2]), "+f"(c[3])
        : "r"(a[0]), "r"(a[1]), "r"(a[2]), "r"(a[3]), "r"(b0), "r"(b1));
}

__device__ __forceinline__ void cp16(uint32_t dst, const void* src) {
    asm volatile("cp.async.cg.shared.global [%0], [%1], 16;"
                 :: "r"(dst), "l"(src));
}
__device__ __forceinline__ void ldsm_x4(uint32_t* r, uint32_t a) {
    asm volatile("ldmatrix.sync.aligned.m8n8.x4.shared.b16 {%0,%1,%2,%3}, [%4];"
                 : "=r"(r[0]), "=r"(r[1]), "=r"(r[2]), "=r"(r[3]) : "r"(a));
}
__device__ __forceinline__ void ldsm_x2(uint32_t* r, uint32_t a) {
    asm volatile("ldmatrix.sync.aligned.m8n8.x2.shared.b16 {%0,%1}, [%2];"
                 : "=r"(r[0]), "=r"(r[1]) : "r"(a));
}

// ---------------------------------------------------------------------------
// Transpose + tf32: W[K][N] -> Wt[N][K]
// ---------------------------------------------------------------------------
__global__ __launch_bounds__(256)
void transpose_tf32(const float* __restrict__ W, float* __restrict__ Wt,
                    int K, int N) {
    __shared__ float tile[32][33];
    int n0 = blockIdx.x * 32, k0 = blockIdx.y * 32;
    int tx = threadIdx.x, ty = threadIdx.y;  // (32, 8)
#pragma unroll
    for (int j = 0; j < 4; j++)
        tile[ty + j * 8][tx] = W[(size_t)(k0 + ty + j * 8) * N + n0 + tx];
    __syncthreads();
#pragma unroll
    for (int j = 0; j < 4; j++)
        Wt[(size_t)(n0 + ty + j * 8) * K + k0 + tx] =
            __uint_as_float(f2tf32(tile[tx][ty + j * 8]));
}

// ---------------------------------------------------------------------------
// TF32 GEMM v5: C[M,N] = tf32(A[M,K]) @ Bt[N,K]^T (+bias) [+fused RoPE]
// A is fp32 (converted to tf32 in the A-staging path via LDG+cvt+STS;
// idempotent if A already holds tf32 bits). Bt holds tf32 bits (cp.async).
// 64x128 tile, 128 threads, BK=32, 2-stage double buffer, 4 CTAs/SM.
// ---------------------------------------------------------------------------
#define V4_A_BYTES 8192            // 64 * 32 * 4
#define V4_B_BYTES 16384           // 128 * 32 * 4
#define V4_STG (V4_A_BYTES + V4_B_BYTES)
#define V4_SMEM (2 * V4_STG)       // 49152

__global__ __launch_bounds__(128, 4)
void gemm_v5(const float* __restrict__ A, const float* __restrict__ Bt,
             const float* __restrict__ bias, float* __restrict__ C,
             int M, int N, int K,
             int fuse_rope,
             const float* __restrict__ fc, const float* __restrict__ fs,
             float* __restrict__ Kg, float* __restrict__ Vg) {
    extern __shared__ __align__(16) char smraw[];
    const uint32_t sbase = (uint32_t)__cvta_generic_to_shared(smraw);

    const int tid = threadIdx.x;
    const int lane = tid & 31;
    const int wid = tid >> 5;
    const int wm = wid >> 1;   // 0..1 -> m offset 32*wm
    const int wn = wid & 1;    // 0..1 -> n offset 64*wn
    const int bm = blockIdx.y * 64, bn = blockIdx.x * 128;

    float acc[2][8][4];
#pragma unroll
    for (int mi = 0; mi < 2; mi++)
#pragma unroll
        for (int ni = 0; ni < 8; ni++)
#pragma unroll
            for (int r = 0; r < 4; r++) acc[mi][ni][r] = 0.f;

    const int srow = tid >> 3;   // 0..15
    const int sk4 = tid & 7;     // 0..7

    // B staging: cp.async (async, tracked by commit groups)
    auto stage_B = [&](int kt, int stg) {
        uint32_t sb = sbase + stg * V4_STG + V4_A_BYTES;
        const float* bp = Bt + (size_t)bn * K + kt * 32 + sk4 * 4;
#pragma unroll
        for (int i = 0; i < 8; i++) {
            int row = srow + i * 16;
            cp16(sb + ((row * 8 + (sk4 ^ (row & 7))) << 4), bp + (size_t)row * K);
        }
        asm volatile("cp.async.commit_group;");
    };
    // A staging: LDG + tf32-convert + STS (visible after next __syncthreads)
    auto stage_A = [&](int kt, int stg) {
        uint32_t sa = sbase + stg * V4_STG;
        const float* ap = A + (size_t)bm * K + kt * 32 + sk4 * 4;
#pragma unroll
        for (int i = 0; i < 4; i++) {
            int row = srow + i * 16;
            float4 v = *(const float4*)(ap + (size_t)row * K);
            uint4 t;
            t.x = f2tf32(v.x); t.y = f2tf32(v.y);
            t.z = f2tf32(v.z); t.w = f2tf32(v.w);
            uint32_t dst = sa + ((row * 8 + (sk4 ^ (row & 7))) << 4);
            asm volatile("st.shared.v4.b32 [%0], {%1,%2,%3,%4};"
                         :: "r"(dst), "r"(t.x), "r"(t.y), "r"(t.z), "r"(t.w));
        }
    };

    const int nkt = K / 32;
    stage_B(0, 0);
    stage_A(0, 0);

    const int mLane = wm * 32 + (lane & 15);   // + mi*16
    const int k4A_base = (lane >> 4);          // + s*2
    const int nLane = wn * 64 + (lane & 7);    // + ni*8
    const int k4B_base = ((lane >> 3) & 1);    // + s*2

    for (int kt = 0; kt < nkt; kt++) {
        int cur = kt & 1;
        asm volatile("cp.async.wait_group 0;");
        __syncthreads();   // A-STS(kt) and B-cp.async(kt) both visible
        if (kt + 1 < nkt) { stage_B(kt + 1, cur ^ 1); stage_A(kt + 1, cur ^ 1); }

        uint32_t aBase = sbase + cur * V4_STG;
        uint32_t bBase = aBase + V4_A_BYTES;
#pragma unroll
        for (int s = 0; s < 4; s++) {
            uint32_t af[2][4];
            int k4a = s * 2 + k4A_base;
#pragma unroll
            for (int mi = 0; mi < 2; mi++) {
                int m = mLane + mi * 16;
                ldsm_x4(af[mi], aBase + ((m * 8 + (k4a ^ (m & 7))) << 4));
            }
            uint32_t bf[8][2];
            int k4b = s * 2 + k4B_base;
#pragma unroll
            for (int ni = 0; ni < 8; ni++) {
                int n = nLane + ni * 8;
                ldsm_x2(bf[ni], bBase + ((n * 8 + (k4b ^ (n & 7))) << 4));
            }
#pragma unroll
            for (int mi = 0; mi < 2; mi++)
#pragma unroll
                for (int ni = 0; ni < 8; ni++)
                    mma_tf32(acc[mi][ni], af[mi], bf[ni][0], bf[ni][1]);
        }
    }

    const int g4 = lane >> 2, a4 = lane & 3;

    bool isKV = false, isV = false;
    int kvh = 0;
    if (fuse_rope && bn >= EE) {
        isKV = true;
        if (bn < EE + KVD) kvh = (bn - EE) >> 7;
        else { isV = true; kvh = (bn - EE - KVD) >> 7; }
    }

    if (!isKV) {
#pragma unroll
        for (int mi = 0; mi < 2; mi++) {
            int row = bm + wm * 32 + mi * 16 + g4;
#pragma unroll
            for (int ni = 0; ni < 8; ni++) {
                int col = bn + wn * 64 + ni * 8 + 2 * a4;
                float bx = 0.f, by = 0.f;
                if (bias) { bx = bias[col]; by = bias[col + 1]; }
                *(float2*)(C + (size_t)row * N + col) =
                    make_float2(acc[mi][ni][0] + bx, acc[mi][ni][1] + by);
                *(float2*)(C + (size_t)(row + 8) * N + col) =
                    make_float2(acc[mi][ni][2] + bx, acc[mi][ni][3] + by);
            }
        }
    } else {
        float* dstBase = isV ? Vg : Kg;
#pragma unroll
        for (int mi = 0; mi < 2; mi++) {
            int row = bm + wm * 32 + mi * 16 + g4;
            int b = row >> 11;
            int t = row & 2047;
            float* dst = dstBase + ((size_t)(b * NKVH + kvh) * TT) * DD;
#pragma unroll
            for (int ni = 0; ni < 8; ni++) {
                int col = bn + wn * 64 + ni * 8 + 2 * a4;
                int d = wn * 64 + ni * 8 + 2 * a4;
                int i = d >> 1;
                float bx = 0.f, by = 0.f;
                if (bias) { bx = bias[col]; by = bias[col + 1]; }
                {
                    float c0 = fc[t * 64 + i], s0 = fs[t * 64 + i];
                    float v0 = acc[mi][ni][0] + bx;
                    float v1 = acc[mi][ni][1] + by;
                    *(float2*)(dst + (size_t)t * DD + d) = make_float2(
                        __uint_as_float(f2tf32(v0 * c0 - v1 * s0)),
                        __uint_as_float(f2tf32(v0 * s0 + v1 * c0)));
                }
                {
                    float c1 = fc[(t + 8) * 64 + i], s1 = fs[(t + 8) * 64 + i];
                    float v0 = acc[mi][ni][2] + bx;
                    float v1 = acc[mi][ni][3] + by;
                    *(float2*)(dst + (size_t)(t + 8) * DD + d) = make_float2(
                        __uint_as_float(f2tf32(v0 * c1 - v1 * s1)),
                        __uint_as_float(f2tf32(v0 * s1 + v1 * c1)));
                }
            }
        }
    }
}

// ---------------------------------------------------------------------------
// TF32 tensor-core flash attention (R4 structure; K/V staging via cp.async
// with IDENTICAL indexing to the verified LDG/STS loop).
// ---------------------------------------------------------------------------
#define QS_S 132
#define KS_S 132
#define VS_S2 136
#define PS_S 68
#define SM_Q  0
#define SM_K  (128 * QS_S)
#define SM_V  (SM_K + 64 * KS_S)
#define SM_P  (SM_V + 64 * VS_S2)
#define SM_TOT (SM_P + 128 * PS_S)

__global__ __launch_bounds__(256, 1)
void attn_tf32(const float* __restrict__ qkv,
               const float* __restrict__ Kg,
               const float* __restrict__ Vg,
               float* __restrict__ Y) {
    extern __shared__ __align__(16) uint32_t smu[];
    uint32_t* Qs = smu + SM_Q;
    uint32_t* Ks = smu + SM_K;
    uint32_t* Vs = smu + SM_V;
    uint32_t* Ps = smu + SM_P;
    const uint32_t sb = (uint32_t)__cvta_generic_to_shared(smu);

    const int tid = threadIdx.x;
    const int lane = tid & 31;
    const int warp = tid >> 5;
    const int g4 = lane >> 2;
    const int a4 = lane & 3;

    const int qtile = (gridDim.x - 1) - blockIdx.x;
    const int bh = blockIdx.y;
    const int b = bh >> 4, h = bh & 15;
    const int kv = h >> 2;

    const float* qbase = qkv + ((size_t)(b * TT + qtile * 128)) * N1 + h * DD;
#pragma unroll
    for (int i = 0; i < 16; i++) {
        int idx = tid + i * 256;
        int row = idx >> 5;
        int col = (idx & 31) * 4;
        float4 q = *(const float4*)(qbase + (size_t)row * N1 + col);
        uint4 t;
        t.x = f2tf32(q.x); t.y = f2tf32(q.y);
        t.z = f2tf32(q.z); t.w = f2tf32(q.w);
        *(uint4*)(Qs + row * QS_S + col) = t;
    }

    float oacc[16][4];
#pragma unroll
    for (int nt = 0; nt < 16; nt++)
#pragma unroll
        for (int r = 0; r < 4; r++) oacc[nt][r] = 0.f;
    float m0 = -1e30f, m1 = -1e30f, l0 = 0.f, l1 = 0.f;

    const float scale = 0.08838834764831845f;
    const float* kbase = Kg + ((size_t)(b * NKVH + kv) * TT) * DD;
    const float* vbase = Vg + ((size_t)(b * NKVH + kv) * TT) * DD;

    const int rloc = warp * 16 + g4;
    const int grow0 = qtile * 128 + rloc;
    const int grow1 = grow0 + 8;

    const int njt = 2 * qtile + 2;
    for (int jt = 0; jt < njt; jt++) {
        __syncthreads();
#pragma unroll
        for (int i = 0; i < 8; i++) {
            int idx = tid + i * 256;
            int tok = idx >> 5;
            int col = (idx & 31) * 4;
            cp16(sb + (uint32_t)(SM_K + tok * KS_S + col) * 4,
                 kbase + (size_t)(jt * 64 + tok) * DD + col);
            cp16(sb + (uint32_t)(SM_V + tok * VS_S2 + col) * 4,
                 vbase + (size_t)(jt * 64 + tok) * DD + col);
        }
        asm volatile("cp.async.commit_group;");
        asm volatile("cp.async.wait_group 0;");
        __syncthreads();

        float sacc[8][4];
#pragma unroll
        for (int nt = 0; nt < 8; nt++)
#pragma unroll
            for (int r = 0; r < 4; r++) sacc[nt][r] = 0.f;

#pragma unroll
        for (int kt = 0; kt < 16; kt++) {
            uint32_t af[4];
            int c = kt * 8 + a4;
            af[0] = Qs[rloc * QS_S + c];
            af[1] = Qs[(rloc + 8) * QS_S + c];
            af[2] = Qs[rloc * QS_S + c + 4];
            af[3] = Qs[(rloc + 8) * QS_S + c + 4];
#pragma unroll
            for (int nt = 0; nt < 8; nt++) {
                int n = nt * 8 + g4;
                mma_tf32(sacc[nt], af, Ks[n * KS_S + kt * 8 + a4],
                         Ks[n * KS_S + kt * 8 + a4 + 4]);
            }
        }

        if (jt >= 2 * qtile) {
#pragma unroll
            for (int nt = 0; nt < 8; nt++) {
                int gc = jt * 64 + nt * 8 + 2 * a4;
                sacc[nt][0] = (gc     > grow0) ? -1e30f : sacc[nt][0] * scale;
                sacc[nt][1] = (gc + 1 > grow0) ? -1e30f : sacc[nt][1] * scale;
                sacc[nt][2] = (gc     > grow1) ? -1e30f : sacc[nt][2] * scale;
                sacc[nt][3] = (gc + 1 > grow1) ? -1e30f : sacc[nt][3] * scale;
            }
        } else {
#pragma unroll
            for (int nt = 0; nt < 8; nt++)
#pragma unroll
                for (int r = 0; r < 4; r++) sacc[nt][r] *= scale;
        }

        float rm0 = -1e30f, rm1 = -1e30f;
#pragma unroll
        for (int nt = 0; nt < 8; nt++) {
            rm0 = fmaxf(rm0, fmaxf(sacc[nt][0], sacc[nt][1]));
            rm1 = fmaxf(rm1, fmaxf(sacc[nt][2], sacc[nt][3]));
        }
        rm0 = fmaxf(rm0, __shfl_xor_sync(0xffffffffu, rm0, 1));
        rm0 = fmaxf(rm0, __shfl_xor_sync(0xffffffffu, rm0, 2));
        rm1 = fmaxf(rm1, __shfl_xor_sync(0xffffffffu, rm1, 1));
        rm1 = fmaxf(rm1, __shfl_xor_sync(0xffffffffu, rm1, 2));

        float mn0 = fmaxf(m0, rm0), mn1 = fmaxf(m1, rm1);
        float corr0 = __expf(m0 - mn0), corr1 = __expf(m1 - mn1);
        m0 = mn0; m1 = mn1;

        float rs0 = 0.f, rs1 = 0.f;
#pragma unroll
        for (int nt = 0; nt < 8; nt++) {
            float p0 = __expf(sacc[nt][0] - mn0);
            float p1 = __expf(sacc[nt][1] - mn0);
            float p2 = __expf(sacc[nt][2] - mn1);
            float p3 = __expf(sacc[nt][3] - mn1);
            rs0 += p0 + p1; rs1 += p2 + p3;
            int cc = nt * 8 + 2 * a4;
            *(uint2*)(Ps + rloc * PS_S + cc) = make_uint2(f2tf32(p0), f2tf32(p1));
            *(uint2*)(Ps + (rloc + 8) * PS_S + cc) = make_uint2(f2tf32(p2), f2tf32(p3));
        }
        rs0 += __shfl_xor_sync(0xffffffffu, rs0, 1);
        rs0 += __shfl_xor_sync(0xffffffffu, rs0, 2);
        rs1 += __shfl_xor_sync(0xffffffffu, rs1, 1);
        rs1 += __shfl_xor_sync(0xffffffffu, rs1, 2);
        l0 = l0 * corr0 + rs0;
        l1 = l1 * corr1 + rs1;

#pragma unroll
        for (int nt = 0; nt < 16; nt++) {
            oacc[nt][0] *= corr0; oacc[nt][1] *= corr0;
            oacc[nt][2] *= corr1; oacc[nt][3] *= corr1;
        }
        __syncwarp();

#pragma unroll
        for (int kt = 0; kt < 8; kt++) {
            uint32_t af[4];
            int c = kt * 8 + a4;
            af[0] = Ps[rloc * PS_S + c];
            af[1] = Ps[(rloc + 8) * PS_S + c];
            af[2] = Ps[rloc * PS_S + c + 4];
            af[3] = Ps[(rloc + 8) * PS_S + c + 4];
#pragma unroll
            for (int nt = 0; nt < 16; nt++) {
                mma_tf32(oacc[nt], af,
                         Vs[(kt * 8 + a4) * VS_S2 + nt * 8 + g4],
                         Vs[(kt * 8 + a4 + 4) * VS_S2 + nt * 8 + g4]);
            }
        }
    }

    float inv0 = 1.f / l0, inv1 = 1.f / l1;
    int t0 = qtile * 128 + rloc;
    float* y0 = Y + ((size_t)(b * TT + t0)) * EE + h * DD;
    float* y1 = Y + ((size_t)(b * TT + t0 + 8)) * EE + h * DD;
#pragma unroll
    for (int nt = 0; nt < 16; nt++) {
        int cc = nt * 8 + 2 * a4;
        *(float2*)(y0 + cc) = make_float2(
            __uint_as_float(f2tf32(oacc[nt][0] * inv0)),
            __uint_as_float(f2tf32(oacc[nt][1] * inv0)));
        *(float2*)(y1 + cc) = make_float2(
            __uint_as_float(f2tf32(oacc[nt][2] * inv1)),
            __uint_as_float(f2tf32(oacc[nt][3] * inv1)));
    }
}

// ---------------------------------------------------------------------------
extern "C" void kernel_launch(void* const* d_in, const int* in_sizes, int n_in,
                              void* d_out, int out_size) {
    const float* x  = (const float*)d_in[0];
    const float* Wa = (const float*)d_in[1];
    const float* ba = (const float*)d_in[2];
    const float* Wp = (const float*)d_in[3];
    const float* fc = (const float*)d_in[4];
    const float* fs = (const float*)d_in[5];
    float* out = (float*)d_out;

    float *qkv, *kg, *vg, *yb, *wat, *wpt;
    cudaGetSymbolAddress((void**)&qkv, g_qkv);
    cudaGetSymbolAddress((void**)&kg, g_k);
    cudaGetSymbolAddress((void**)&vg, g_v);
    cudaGetSymbolAddress((void**)&yb, g_y);
    cudaGetSymbolAddress((void**)&wat, g_wat);
    cudaGetSymbolAddress((void**)&wpt, g_wpt);

    // operand prep (weights only; x converted in-GEMM now)
    transpose_tf32<<<dim3(N1 / 32, EE / 32), dim3(32, 8)>>>(Wa, wat, EE, N1);
    transpose_tf32<<<dim3(EE / 32, EE / 32), dim3(32, 8)>>>(Wp, wpt, EE, EE);

    cudaFuncSetAttribute(gemm_v5, cudaFuncAttributeMaxDynamicSharedMemorySize,
                         V4_SMEM);

    // 1) QKV GEMM (+bias) with fused RoPE epilogue; A = raw x (fp32)
    gemm_v5<<<dim3(N1 / 128, MM / 64), 128, V4_SMEM>>>(
        x, wat, ba, qkv, MM, N1, EE, 1, fc, fs, kg, vg);

    // 2) attention
    int smem_bytes = SM_TOT * (int)sizeof(uint32_t);
    cudaFuncSetAttribute(attn_tf32, cudaFuncAttributeMaxDynamicSharedMemorySize,
                         smem_bytes);
    attn_tf32<<<dim3(TT / 128, BB * HH), 256, smem_bytes>>>(qkv, kg, vg, yb);

    // 3) output projection; A = yb (tf32 bits; conversion idempotent)
    gemm_v5<<<dim3(EE / 128, MM / 64), 128, V4_SMEM>>>(
        yb, wpt, nullptr, out, MM, EE, EE, 0, nullptr, nullptr, nullptr, nullptr);
}

// round 14
// speedup vs baseline: 1.0790x; 1.0790x over previous
#include <cuda_runtime.h>
#include <cuda_bf16.h>
#include <math.h>
#include <stdint.h>

// Problem constants (QwenGroupedQueryAttention_44100724195922)
#define BB   2
#define TT   2048
#define EE   2048
#define HH   16
#define DD   128
#define GG   4
#define NKVH 4
#define KVD  512
#define N1   3072
#define MM   4096

__device__ float g_qkv[(size_t)MM * N1];             // fp32 (Q region used)
__device__ float g_k[(size_t)BB * NKVH * TT * DD];   // tf32 bits
__device__ float g_v[(size_t)BB * NKVH * TT * DD];   // tf32 bits
__device__ float g_y[(size_t)MM * EE];               // tf32 bits (attn out)
__device__ float g_xt[(size_t)MM * EE];              // x as tf32 bits
__device__ float g_wat[(size_t)N1 * EE];             // Wa^T [N1][E] tf32 bits
__device__ float g_wpt[(size_t)EE * EE];             // Wp^T [E][E] tf32 bits

__device__ __forceinline__ uint32_t f2tf32(float x) {
    uint32_t r;
    asm("cvt.rna.tf32.f32 %0, %1;" : "=r"(r) : "f"(x));
    return r;
}

__device__ __forceinline__ void mma_tf32(float c[4], const uint32_t a[4],
                                         uint32_t b0, uint32_t b1) {
    asm volatile(
        "mma.sync.aligned.m16n8k8.row.col.f32.tf32.tf32.f32 "
        "{%0,%1,%2,%3}, {%4,%5,%6,%7}, {%8,%9}, {%0,%1,%2,%3};"
        : "+f"(c[0]), "+f"(c[1]), "+f"(c[2]), "+f"(c[3])
        : "r"(a[0]), "r"(a[1]), "r"(a[2]), "r"(a[3]), "r"(b0), "r"(b1));
}

__device__ __forceinline__ void cp16(uint32_t dst, const void* src) {
    asm volatile("cp.async.cg.shared.global [%0], [%1], 16;"
                 :: "r"(dst), "l"(src));
}
__device__ __forceinline__ void ldsm_x4(uint32_t* r, uint32_t a) {
    asm volatile("ldmatrix.sync.aligned.m8n8.x4.shared.b16 {%0,%1,%2,%3}, [%4];"
                 : "=r"(r[0]), "=r"(r[1]), "=r"(r[2]), "=r"(r[3]) : "r"(a));
}
__device__ __forceinline__ void ldsm_x2(uint32_t* r, uint32_t a) {
    asm volatile("ldmatrix.sync.aligned.m8n8.x2.shared.b16 {%0,%1}, [%2];"
                 : "=r"(r[0]), "=r"(r[1]) : "r"(a));
}

// ---------------------------------------------------------------------------
// Elementwise fp32 -> tf32 bits
// ---------------------------------------------------------------------------
__global__ __launch_bounds__(256)
void conv_tf32(const float* __restrict__ in, float* __restrict__ out, int n4) {
    int i = blockIdx.x * 256 + threadIdx.x;
    if (i >= n4) return;
    float4 v = ((const float4*)in)[i];
    uint4 t;
    t.x = f2tf32(v.x); t.y = f2tf32(v.y); t.z = f2tf32(v.z); t.w = f2tf32(v.w);
    ((uint4*)out)[i] = t;
}

// ---------------------------------------------------------------------------
// Transpose + tf32: W[K][N] -> Wt[N][K]
// ---------------------------------------------------------------------------
__global__ __launch_bounds__(256)
void transpose_tf32(const float* __restrict__ W, float* __restrict__ Wt,
                    int K, int N) {
    __shared__ float tile[32][33];
    int n0 = blockIdx.x * 32, k0 = blockIdx.y * 32;
    int tx = threadIdx.x, ty = threadIdx.y;  // (32, 8)
#pragma unroll
    for (int j = 0; j < 4; j++)
        tile[ty + j * 8][tx] = W[(size_t)(k0 + ty + j * 8) * N + n0 + tx];
    __syncthreads();
#pragma unroll
    for (int j = 0; j < 4; j++)
        Wt[(size_t)(n0 + ty + j * 8) * K + k0 + tx] =
            __uint_as_float(f2tf32(tile[tx][ty + j * 8]));
}

// ---------------------------------------------------------------------------
// TF32 GEMM v4 + fused RoPE epilogue (R12 verified version).
// ---------------------------------------------------------------------------
#define V4_A_BYTES 8192
#define V4_B_BYTES 16384
#define V4_STG (V4_A_BYTES + V4_B_BYTES)
#define V4_SMEM (2 * V4_STG)

__global__ __launch_bounds__(128, 4)
void gemm_v4(const float* __restrict__ A, const float* __restrict__ Bt,
             const float* __restrict__ bias, float* __restrict__ C,
             int M, int N, int K,
             int fuse_rope,
             const float* __restrict__ fc, const float* __restrict__ fs,
             float* __restrict__ Kg, float* __restrict__ Vg) {
    extern __shared__ __align__(16) char smraw[];
    const uint32_t sbase = (uint32_t)__cvta_generic_to_shared(smraw);

    const int tid = threadIdx.x;
    const int lane = tid & 31;
    const int wid = tid >> 5;
    const int wm = wid >> 1;
    const int wn = wid & 1;
    const int bm = blockIdx.y * 64, bn = blockIdx.x * 128;

    float acc[2][8][4];
#pragma unroll
    for (int mi = 0; mi < 2; mi++)
#pragma unroll
        for (int ni = 0; ni < 8; ni++)
#pragma unroll
            for (int r = 0; r < 4; r++) acc[mi][ni][r] = 0.f;

    const int srow = tid >> 3;
    const int sk4 = tid & 7;

    auto stage_fn = [&](int kt, int stg) {
        uint32_t sa = sbase + stg * V4_STG;
        uint32_t sb = sa + V4_A_BYTES;
        const float* ap = A + (size_t)bm * K + kt * 32 + sk4 * 4;
        const float* bp = Bt + (size_t)bn * K + kt * 32 + sk4 * 4;
#pragma unroll
        for (int i = 0; i < 4; i++) {
            int row = srow + i * 16;
            cp16(sa + ((row * 8 + (sk4 ^ (row & 7))) << 4), ap + (size_t)row * K);
        }
#pragma unroll
        for (int i = 0; i < 8; i++) {
            int row = srow + i * 16;
            cp16(sb + ((row * 8 + (sk4 ^ (row & 7))) << 4), bp + (size_t)row * K);
        }
        asm volatile("cp.async.commit_group;");
    };

    const int nkt = K / 32;
    stage_fn(0, 0);

    const int mLane = wm * 32 + (lane & 15);
    const int k4A_base = (lane >> 4);
    const int nLane = wn * 64 + (lane & 7);
    const int k4B_base = ((lane >> 3) & 1);

    for (int kt = 0; kt < nkt; kt++) {
        int cur = kt & 1;
        asm volatile("cp.async.wait_group 0;");
        __syncthreads();
        if (kt + 1 < nkt) stage_fn(kt + 1, cur ^ 1);

        uint32_t aBase = sbase + cur * V4_STG;
        uint32_t bBase = aBase + V4_A_BYTES;
#pragma unroll
        for (int s = 0; s < 4; s++) {
            uint32_t af[2][4];
            int k4a = s * 2 + k4A_base;
#pragma unroll
            for (int mi = 0; mi < 2; mi++) {
                int m = mLane + mi * 16;
                ldsm_x4(af[mi], aBase + ((m * 8 + (k4a ^ (m & 7))) << 4));
            }
            uint32_t bf[8][2];
            int k4b = s * 2 + k4B_base;
#pragma unroll
            for (int ni = 0; ni < 8; ni++) {
                int n = nLane + ni * 8;
                ldsm_x2(bf[ni], bBase + ((n * 8 + (k4b ^ (n & 7))) << 4));
            }
#pragma unroll
            for (int mi = 0; mi < 2; mi++)
#pragma unroll
                for (int ni = 0; ni < 8; ni++)
                    mma_tf32(acc[mi][ni], af[mi], bf[ni][0], bf[ni][1]);
        }
    }

    const int g4 = lane >> 2, a4 = lane & 3;

    bool isKV = false, isV = false;
    int kvh = 0;
    if (fuse_rope && bn >= EE) {
        isKV = true;
        if (bn < EE + KVD) kvh = (bn - EE) >> 7;
        else { isV = true; kvh = (bn - EE - KVD) >> 7; }
    }

    if (!isKV) {
#pragma unroll
        for (int mi = 0; mi < 2; mi++) {
            int row = bm + wm * 32 + mi * 16 + g4;
#pragma unroll
            for (int ni = 0; ni < 8; ni++) {
                int col = bn + wn * 64 + ni * 8 + 2 * a4;
                float bx = 0.f, by = 0.f;
                if (bias) { bx = bias[col]; by = bias[col + 1]; }
                *(float2*)(C + (size_t)row * N + col) =
                    make_float2(acc[mi][ni][0] + bx, acc[mi][ni][1] + by);
                *(float2*)(C + (size_t)(row + 8) * N + col) =
                    make_float2(acc[mi][ni][2] + bx, acc[mi][ni][3] + by);
            }
        }
    } else {
        float* dstBase = isV ? Vg : Kg;
#pragma unroll
        for (int mi = 0; mi < 2; mi++) {
            int row = bm + wm * 32 + mi * 16 + g4;
            int b = row >> 11;
            int t = row & 2047;
            float* dst = dstBase + ((size_t)(b * NKVH + kvh) * TT) * DD;
#pragma unroll
            for (int ni = 0; ni < 8; ni++) {
                int col = bn + wn * 64 + ni * 8 + 2 * a4;
                int d = wn * 64 + ni * 8 + 2 * a4;
                int i = d >> 1;
                float bx = 0.f, by = 0.f;
                if (bias) { bx = bias[col]; by = bias[col + 1]; }
                {
                    float c0 = fc[t * 64 + i], s0 = fs[t * 64 + i];
                    float v0 = acc[mi][ni][0] + bx;
                    float v1 = acc[mi][ni][1] + by;
                    *(float2*)(dst + (size_t)t * DD + d) = make_float2(
                        __uint_as_float(f2tf32(v0 * c0 - v1 * s0)),
                        __uint_as_float(f2tf32(v0 * s0 + v1 * c0)));
                }
                {
                    float c1 = fc[(t + 8) * 64 + i], s1 = fs[(t + 8) * 64 + i];
                    float v0 = acc[mi][ni][2] + bx;
                    float v1 = acc[mi][ni][3] + by;
                    *(float2*)(dst + (size_t)(t + 8) * DD + d) = make_float2(
                        __uint_as_float(f2tf32(v0 * c1 - v1 * s1)),
                        __uint_as_float(f2tf32(v0 * s1 + v1 * c1)));
                }
            }
        }
    }
}

// ---------------------------------------------------------------------------
// TF32 tensor-core flash attention.
// R12 structure, ONE change: K tile stored in XOR-swizzled k32-planes and
// K fragments loaded via ldmatrix.x4 (verified gemm_v2b B-x4 mapping).
// Q, V, P paths and all arithmetic unchanged.
// ---------------------------------------------------------------------------
#define QS_S 132
#define VS_S2 136
#define PS_S 68
#define SM_Q  0
#define SM_K  (128 * QS_S)                 // K: 4 planes x 2048 words = 8192
#define SM_V  (SM_K + 8192)
#define SM_P  (SM_V + 64 * VS_S2)
#define SM_TOT (SM_P + 128 * PS_S)

__global__ __launch_bounds__(256, 1)
void attn_tf32(const float* __restrict__ qkv,
               const float* __restrict__ Kg,
               const float* __restrict__ Vg,
               float* __restrict__ Y) {
    extern __shared__ __align__(16) uint32_t smu[];
    uint32_t* Qs = smu + SM_Q;
    uint32_t* Vs = smu + SM_V;
    uint32_t* Ps = smu + SM_P;
    const uint32_t sb = (uint32_t)__cvta_generic_to_shared(smu);
    const uint32_t kByteBase = sb + SM_K * 4;

    const int tid = threadIdx.x;
    const int lane = tid & 31;
    const int warp = tid >> 5;
    const int g4 = lane >> 2;
    const int a4 = lane & 3;

    const int qtile = (gridDim.x - 1) - blockIdx.x;
    const int bh = blockIdx.y;
    const int b = bh >> 4, h = bh & 15;
    const int kv = h >> 2;

    const float* qbase = qkv + ((size_t)(b * TT + qtile * 128)) * N1 + h * DD;
#pragma unroll
    for (int i = 0; i < 16; i++) {
        int idx = tid + i * 256;
        int row = idx >> 5;
        int col = (idx & 31) * 4;
        float4 q = *(const float4*)(qbase + (size_t)row * N1 + col);
        uint4 t;
        t.x = f2tf32(q.x); t.y = f2tf32(q.y);
        t.z = f2tf32(q.z); t.w = f2tf32(q.w);
        *(uint4*)(Qs + row * QS_S + col) = t;
    }

    float oacc[16][4];
#pragma unroll
    for (int nt = 0; nt < 16; nt++)
#pragma unroll
        for (int r = 0; r < 4; r++) oacc[nt][r] = 0.f;
    float m0 = -1e30f, m1 = -1e30f, l0 = 0.f, l1 = 0.f;

    const float scale = 0.08838834764831845f;
    const float* kbase = Kg + ((size_t)(b * NKVH + kv) * TT) * DD;
    const float* vbase = Vg + ((size_t)(b * NKVH + kv) * TT) * DD;

    const int rloc = warp * 16 + g4;
    const int grow0 = qtile * 128 + rloc;
    const int grow1 = grow0 + 8;
    const int nL = lane & 15;       // n within 16-group (ldsm x4)
    const int k4hi = lane >> 4;     // 0/1

    const int njt = 2 * qtile + 2;
    for (int jt = 0; jt < njt; jt++) {
        __syncthreads();
#pragma unroll
        for (int i = 0; i < 8; i++) {
            int idx = tid + i * 256;
            int tok = idx >> 5;
            int col4 = idx & 31;   // 16B chunk index (4 floats)
            const float4* kp = (const float4*)(kbase + (size_t)(jt * 64 + tok) * DD + col4 * 4);
            const float4* vp = (const float4*)(vbase + (size_t)(jt * 64 + tok) * DD + col4 * 4);
            // K: plane (col4>>3), chunk (col4&7), XOR-swizzled
            int pl = col4 >> 3, c4 = col4 & 7;
            *(uint4*)((char*)smu + (SM_K << 2) + pl * 8192 + tok * 128 +
                      ((c4 ^ (tok & 7)) << 4)) = *(const uint4*)kp;
            *(uint4*)(Vs + tok * VS_S2 + col4 * 4) = *(const uint4*)vp;
        }
        __syncthreads();

        float sacc[8][4];
#pragma unroll
        for (int nt = 0; nt < 8; nt++)
#pragma unroll
            for (int r = 0; r < 4; r++) sacc[nt][r] = 0.f;

#pragma unroll
        for (int kt = 0; kt < 16; kt++) {
            uint32_t af[4];
            int c = kt * 8 + a4;
            af[0] = Qs[rloc * QS_S + c];
            af[1] = Qs[(rloc + 8) * QS_S + c];
            af[2] = Qs[rloc * QS_S + c + 4];
            af[3] = Qs[(rloc + 8) * QS_S + c + 4];
            int pl = kt >> 2;
            int k4 = (kt & 3) * 2 + k4hi;
#pragma unroll
            for (int bi = 0; bi < 4; bi++) {
                int n = bi * 16 + nL;
                uint32_t bf[4];
                ldsm_x4(bf, kByteBase + pl * 8192 + n * 128 +
                                ((k4 ^ (n & 7)) << 4));
                mma_tf32(sacc[bi * 2 + 0], af, bf[0], bf[2]);
                mma_tf32(sacc[bi * 2 + 1], af, bf[1], bf[3]);
            }
        }

        if (jt >= 2 * qtile) {
#pragma unroll
            for (int nt = 0; nt < 8; nt++) {
                int gc = jt * 64 + nt * 8 + 2 * a4;
                sacc[nt][0] = (gc     > grow0) ? -1e30f : sacc[nt][0] * scale;
                sacc[nt][1] = (gc + 1 > grow0) ? -1e30f : sacc[nt][1] * scale;
                sacc[nt][2] = (gc     > grow1) ? -1e30f : sacc[nt][2] * scale;
                sacc[nt][3] = (gc + 1 > grow1) ? -1e30f : sacc[nt][3] * scale;
            }
        } else {
#pragma unroll
            for (int nt = 0; nt < 8; nt++)
#pragma unroll
                for (int r = 0; r < 4; r++) sacc[nt][r] *= scale;
        }

        float rm0 = -1e30f, rm1 = -1e30f;
#pragma unroll
        for (int nt = 0; nt < 8; nt++) {
            rm0 = fmaxf(rm0, fmaxf(sacc[nt][0], sacc[nt][1]));
            rm1 = fmaxf(rm1, fmaxf(sacc[nt][2], sacc[nt][3]));
        }
        rm0 = fmaxf(rm0, __shfl_xor_sync(0xffffffffu, rm0, 1));
        rm0 = fmaxf(rm0, __shfl_xor_sync(0xffffffffu, rm0, 2));
        rm1 = fmaxf(rm1, __shfl_xor_sync(0xffffffffu, rm1, 1));
        rm1 = fmaxf(rm1, __shfl_xor_sync(0xffffffffu, rm1, 2));

        float mn0 = fmaxf(m0, rm0), mn1 = fmaxf(m1, rm1);
        float corr0 = __expf(m0 - mn0), corr1 = __expf(m1 - mn1);
        m0 = mn0; m1 = mn1;

        float rs0 = 0.f, rs1 = 0.f;
#pragma unroll
        for (int nt = 0; nt < 8; nt++) {
            float p0 = __expf(sacc[nt][0] - mn0);
            float p1 = __expf(sacc[nt][1] - mn0);
            float p2 = __expf(sacc[nt][2] - mn1);
            float p3 = __expf(sacc[nt][3] - mn1);
            rs0 += p0 + p1; rs1 += p2 + p3;
            int cc = nt * 8 + 2 * a4;
            *(uint2*)(Ps + rloc * PS_S + cc) = make_uint2(f2tf32(p0), f2tf32(p1));
            *(uint2*)(Ps + (rloc + 8) * PS_S + cc) = make_uint2(f2tf32(p2), f2tf32(p3));
        }
        rs0 += __shfl_xor_sync(0xffffffffu, rs0, 1);
        rs0 += __shfl_xor_sync(0xffffffffu, rs0, 2);
        rs1 += __shfl_xor_sync(0xffffffffu, rs1, 1);
        rs1 += __shfl_xor_sync(0xffffffffu, rs1, 2);
        l0 = l0 * corr0 + rs0;
        l1 = l1 * corr1 + rs1;

#pragma unroll
        for (int nt = 0; nt < 16; nt++) {
            oacc[nt][0] *= corr0; oacc[nt][1] *= corr0;
            oacc[nt][2] *= corr1; oacc[nt][3] *= corr1;
        }
        __syncwarp();

#pragma unroll
        for (int kt = 0; kt < 8; kt++) {
            uint32_t af[4];
            int c = kt * 8 + a4;
            af[0] = Ps[rloc * PS_S + c];
            af[1] = Ps[(rloc + 8) * PS_S + c];
            af[2] = Ps[rloc * PS_S + c + 4];
            af[3] = Ps[(rloc + 8) * PS_S + c + 4];
#pragma unroll
            for (int nt = 0; nt < 16; nt++) {
                mma_tf32(oacc[nt], af,
                         Vs[(kt * 8 + a4) * VS_S2 + nt * 8 + g4],
                         Vs[(kt * 8 + a4 + 4) * VS_S2 + nt * 8 + g4]);
            }
        }
    }

    float inv0 = 1.f / l0, inv1 = 1.f / l1;
    int t0 = qtile * 128 + rloc;
    float* y0 = Y + ((size_t)(b * TT + t0)) * EE + h * DD;
    float* y1 = Y + ((size_t)(b * TT + t0 + 8)) * EE + h * DD;
#pragma unroll
    for (int nt = 0; nt < 16; nt++) {
        int cc = nt * 8 + 2 * a4;
        *(float2*)(y0 + cc) = make_float2(
            __uint_as_float(f2tf32(oacc[nt][0] * inv0)),
            __uint_as_float(f2tf32(oacc[nt][1] * inv0)));
        *(float2*)(y1 + cc) = make_float2(
            __uint_as_float(f2tf32(oacc[nt][2] * inv1)),
            __uint_as_float(f2tf32(oacc[nt][3] * inv1)));
    }
}

// ---------------------------------------------------------------------------
extern "C" void kernel_launch(void* const* d_in, const int* in_sizes, int n_in,
                              void* d_out, int out_size) {
    const float* x  = (const float*)d_in[0];
    const float* Wa = (const float*)d_in[1];
    const float* ba = (const float*)d_in[2];
    const float* Wp = (const float*)d_in[3];
    const float* fc = (const float*)d_in[4];
    const float* fs = (const float*)d_in[5];
    float* out = (float*)d_out;

    float *qkv, *kg, *vg, *yb, *xt, *wat, *wpt;
    cudaGetSymbolAddress((void**)&qkv, g_qkv);
    cudaGetSymbolAddress((void**)&kg, g_k);
    cudaGetSymbolAddress((void**)&vg, g_v);
    cudaGetSymbolAddress((void**)&yb, g_y);
    cudaGetSymbolAddress((void**)&xt, g_xt);
    cudaGetSymbolAddress((void**)&wat, g_wat);
    cudaGetSymbolAddress((void**)&wpt, g_wpt);

    // operand prep
    conv_tf32<<<(MM * EE / 4 + 255) / 256, 256>>>(x, xt, MM * EE / 4);
    transpose_tf32<<<dim3(N1 / 32, EE / 32), dim3(32, 8)>>>(Wa, wat, EE, N1);
    transpose_tf32<<<dim3(EE / 32, EE / 32), dim3(32, 8)>>>(Wp, wpt, EE, EE);

    cudaFuncSetAttribute(gemm_v4, cudaFuncAttributeMaxDynamicSharedMemorySize,
                         V4_SMEM);

    // 1) QKV GEMM (+bias) with fused RoPE epilogue
    gemm_v4<<<dim3(N1 / 128, MM / 64), 128, V4_SMEM>>>(
        xt, wat, ba, qkv, MM, N1, EE, 1, fc, fs, kg, vg);

    // 2) attention
    int smem_bytes = SM_TOT * (int)sizeof(uint32_t);
    cudaFuncSetAttribute(attn_tf32, cudaFuncAttributeMaxDynamicSharedMemorySize,
                         smem_bytes);
    attn_tf32<<<dim3(TT / 128, BB * HH), 256, smem_bytes>>>(qkv, kg, vg, yb);

    // 3) output projection
    gemm_v4<<<dim3(EE / 128, MM / 64), 128, V4_SMEM>>>(
        yb, wpt, nullptr, out, MM, EE, EE, 0, nullptr, nullptr, nullptr, nullptr);
}